// round 13
// baseline (speedup 1.0000x reference)
#include <cuda_runtime.h>

#define L_SEQ 256
#define D_HEAD 64
#define MASK_VAL (-4294967295.0f)   // -2^32 + 1

__device__ __forceinline__ float4 ldcg4(const float4* p) {
    float4 r;
    asm volatile("ld.global.cg.v4.f32 {%0,%1,%2,%3}, [%4];"
                 : "=f"(r.x), "=f"(r.y), "=f"(r.z), "=f"(r.w) : "l"(p));
    return r;
}

// One CTA per (b, h, q) row. 256 threads, 6 CTAs/SM.
// R10 config; streaming tensors (TMK/TMV) loaded with .cg (L1 bypass).
__global__ __launch_bounds__(256, 6)
void tasdp_kernel(const float* __restrict__ Q,
                  const float* __restrict__ Km,
                  const float* __restrict__ V,
                  const float* __restrict__ TMK,
                  const float* __restrict__ TMV,
                  const float* __restrict__ AM,          // attn_mask [L,L]
                  const unsigned char* __restrict__ PM,  // padding_mask [b,L] (bool)
                  float* __restrict__ O,                 // [b,h,L,D]
                  float* __restrict__ AW,                // [b,h,L,L]
                  int H, int write_aw)
{
    const int bhq = blockIdx.x;          // b*h*L + q  (flattened)
    const int q   = bhq & (L_SEQ - 1);
    const int bh  = bhq >> 8;
    const int b   = bh / H;

    __shared__ float  qsh[D_HEAD];
    __shared__ float  esh[L_SEQ];
    __shared__ float  red[8];
    __shared__ float4 acc_sh[16][16];

    const int tid  = threadIdx.x;
    const int w    = tid >> 5;
    const int lane = tid & 31;
    const int f4   = lane & 15;          // float4 chunk within d (16*4 = 64)
    const int grp  = lane >> 4;          // which of 2 k-rows this half-warp owns

    // ---- load Q row into shared ----
    if (tid < D_HEAD) qsh[tid] = Q[(size_t)bhq * D_HEAD + tid];
    __syncthreads();

    // ---- Phase A: energy[k] = ((K[k] + TMK[q,k]) . Q[q]) / sqrt(d) + mask ----
    const float4 q4 = ((const float4*)qsh)[f4];
    const int krow0 = 2 * w + grp;                 // this half-warp's first k row
    const float4* tptr = (const float4*)(TMK + (size_t)bhq * L_SEQ * D_HEAD)
                         + (krow0 * 16 + f4);
    const float4* kptr = (const float4*)(Km  + (size_t)bh  * L_SEQ * D_HEAD)
                         + (krow0 * 16 + f4);
    const float*         amrow = AM + q * L_SEQ;
    const unsigned char* pmrow = PM + b * L_SEQ;

    #pragma unroll 4
    for (int it = 0; it < L_SEQ / 16; ++it) {
        float4 t  = ldcg4(tptr);       // streaming, L1 bypass
        float4 kk = __ldg(kptr);       // hot in L1/L2
        tptr += 256;                   // 16 rows * 16 float4
        kptr += 256;
        float s = (t.x + kk.x) * q4.x + (t.y + kk.y) * q4.y
                + (t.z + kk.z) * q4.z + (t.w + kk.w) * q4.w;
        s += __shfl_xor_sync(0xffffffffu, s, 1);
        s += __shfl_xor_sync(0xffffffffu, s, 2);
        s += __shfl_xor_sync(0xffffffffu, s, 4);
        s += __shfl_xor_sync(0xffffffffu, s, 8);
        if (f4 == 0) {
            const int k = it * 16 + krow0;
            float e = s * 0.125f + amrow[k];        // 1/sqrt(64) = 0.125
            if (pmrow[k]) e = MASK_VAL;
            esh[k] = e;
        }
    }

    // ---- Prefetch first phase-B iteration (addresses independent of softmax) ----
    const int bf4 = tid & 15;        // float4 index over d
    const int kg  = tid >> 4;        // 16 k-groups
    const float4* tvp = (const float4*)(TMV + (size_t)bhq * L_SEQ * D_HEAD)
                        + (kg * 16 + bf4);
    const float4* vvp = (const float4*)(V   + (size_t)bh  * L_SEQ * D_HEAD)
                        + (kg * 16 + bf4);
    float4 pf_t = ldcg4(tvp);        // in flight across the softmax window
    float4 pf_v = __ldg(vvp);
    tvp += 256;
    vvp += 256;

    __syncthreads();

    // ---- Softmax over k (256 values, one per thread) ----
    const float v = esh[tid];
    float m = v;
    #pragma unroll
    for (int o = 16; o > 0; o >>= 1)
        m = fmaxf(m, __shfl_xor_sync(0xffffffffu, m, o));
    if (lane == 0) red[w] = m;
    __syncthreads();
    if (tid == 0) {
        float mm = red[0];
        #pragma unroll
        for (int i = 1; i < 8; ++i) mm = fmaxf(mm, red[i]);
        red[0] = mm;
    }
    __syncthreads();
    m = red[0];
    __syncthreads();

    const float e = __expf(v - m);
    float s = e;
    #pragma unroll
    for (int o = 16; o > 0; o >>= 1)
        s += __shfl_xor_sync(0xffffffffu, s, o);
    if (lane == 0) red[w] = s;
    __syncthreads();
    if (tid == 0) {
        float ss = red[0];
        #pragma unroll
        for (int i = 1; i < 8; ++i) ss += red[i];
        red[0] = 1.0f / ss;
    }
    __syncthreads();
    const float a = e * red[0];
    __syncthreads();
    esh[tid] = a;
    if (write_aw) AW[(size_t)bhq * L_SEQ + tid] = a;
    __syncthreads();

    // ---- Phase B: O[q,:] = sum_k a[k] * (V[k,:] + TMV[q,k,:]) ----
    float4 acc;
    {
        const float ak0 = esh[kg];               // consume prefetched iteration
        acc.x = ak0 * (pf_t.x + pf_v.x);
        acc.y = ak0 * (pf_t.y + pf_v.y);
        acc.z = ak0 * (pf_t.z + pf_v.z);
        acc.w = ak0 * (pf_t.w + pf_v.w);
    }

    #pragma unroll 3
    for (int k = kg + 16; k < L_SEQ; k += 16) {
        const float ak = esh[k];
        float4 t  = ldcg4(tvp);      // streaming, L1 bypass
        float4 vv = __ldg(vvp);      // hot in L1/L2
        tvp += 256;
        vvp += 256;
        acc.x += ak * (t.x + vv.x);
        acc.y += ak * (t.y + vv.y);
        acc.z += ak * (t.z + vv.z);
        acc.w += ak * (t.w + vv.w);
    }
    acc_sh[kg][bf4] = acc;
    __syncthreads();

    if (tid < 16) {
        float4 r = acc_sh[0][tid];
        #pragma unroll
        for (int g = 1; g < 16; ++g) {
            float4 p = acc_sh[g][tid];
            r.x += p.x; r.y += p.y; r.z += p.z; r.w += p.w;
        }
        ((float4*)(O + (size_t)bhq * D_HEAD))[tid] = r;
    }
}

extern "C" void kernel_launch(void* const* d_in, const int* in_sizes, int n_in,
                              void* d_out, int out_size)
{
    const float*         Q   = (const float*)d_in[0];
    const float*         Km  = (const float*)d_in[1];
    const float*         V   = (const float*)d_in[2];
    const float*         TMK = (const float*)d_in[3];
    const float*         TMV = (const float*)d_in[4];
    const float*         AM  = (const float*)d_in[5];
    const unsigned char* PM  = (const unsigned char*)d_in[6];

    const int L = 256, D = 64;
    const int b = in_sizes[6] / L;                 // padding_mask is [b, L]
    const int h = in_sizes[0] / (b * L * D);       // Q is [b, h, L, D]

    const int nO  = b * h * L * D;
    const int nAW = b * h * L * L;

    float* O  = (float*)d_out;
    float* AW = O + nO;
    const int write_aw = (out_size >= nO + nAW) ? 1 : 0;

    tasdp_kernel<<<b * h * L, 256>>>(Q, Km, V, TMK, TMV, AM, PM, O, AW, h, write_aw);
}

// round 14
// speedup vs baseline: 1.0735x; 1.0735x over previous
#include <cuda_runtime.h>

#define L_SEQ 256
#define D_HEAD 64
#define MASK_VAL (-4294967295.0f)   // -2^32 + 1

// One CTA per (b, h, q) row. 256 threads, 6 CTAs/SM.  (R3 + phase-B prefetch)
__global__ __launch_bounds__(256, 6)
void tasdp_kernel(const float* __restrict__ Q,
                  const float* __restrict__ Km,
                  const float* __restrict__ V,
                  const float* __restrict__ TMK,
                  const float* __restrict__ TMV,
                  const float* __restrict__ AM,          // attn_mask [L,L]
                  const unsigned char* __restrict__ PM,  // padding_mask [b,L] (bool)
                  float* __restrict__ O,                 // [b,h,L,D]
                  float* __restrict__ AW,                // [b,h,L,L]
                  int H, int write_aw)
{
    const int bhq = blockIdx.x;          // b*h*L + q  (flattened)
    const int q   = bhq & (L_SEQ - 1);
    const int bh  = bhq >> 8;
    const int b   = bh / H;

    __shared__ float  qsh[D_HEAD];
    __shared__ float  esh[L_SEQ];
    __shared__ float  red[8];
    __shared__ float4 acc_sh[16][16];

    const int tid  = threadIdx.x;
    const int w    = tid >> 5;
    const int lane = tid & 31;
    const int f4   = lane & 15;          // float4 chunk within d (16*4 = 64)
    const int grp  = lane >> 4;          // which of 2 k-rows this half-warp owns

    // ---- load Q row into shared ----
    if (tid < D_HEAD) qsh[tid] = Q[(size_t)bhq * D_HEAD + tid];
    __syncthreads();

    // ---- Phase A: energy[k] = ((K[k] + TMK[q,k]) . Q[q]) / sqrt(d) + mask ----
    const float4 q4 = ((const float4*)qsh)[f4];
    const int krow0 = 2 * w + grp;                 // this half-warp's first k row
    const float4* tptr = (const float4*)(TMK + (size_t)bhq * L_SEQ * D_HEAD)
                         + (krow0 * 16 + f4);
    const float4* kptr = (const float4*)(Km  + (size_t)bh  * L_SEQ * D_HEAD)
                         + (krow0 * 16 + f4);
    const float*         amrow = AM + q * L_SEQ;
    const unsigned char* pmrow = PM + b * L_SEQ;

    #pragma unroll 4
    for (int it = 0; it < L_SEQ / 16; ++it) {
        float4 t  = __ldcs(tptr);      // streaming, no reuse
        float4 kk = __ldg(kptr);       // hot in L2
        tptr += 256;                   // 16 rows * 16 float4
        kptr += 256;
        float s = (t.x + kk.x) * q4.x + (t.y + kk.y) * q4.y
                + (t.z + kk.z) * q4.z + (t.w + kk.w) * q4.w;
        s += __shfl_xor_sync(0xffffffffu, s, 1);
        s += __shfl_xor_sync(0xffffffffu, s, 2);
        s += __shfl_xor_sync(0xffffffffu, s, 4);
        s += __shfl_xor_sync(0xffffffffu, s, 8);
        if (f4 == 0) {
            const int k = it * 16 + krow0;
            float e = s * 0.125f + amrow[k];        // 1/sqrt(64) = 0.125
            if (pmrow[k]) e = MASK_VAL;
            esh[k] = e;
        }
    }

    // ---- Prefetch first phase-B iteration (addresses independent of softmax) ----
    const int bf4 = tid & 15;        // float4 index over d
    const int kg  = tid >> 4;        // 16 k-groups
    const float4* tvp = (const float4*)(TMV + (size_t)bhq * L_SEQ * D_HEAD)
                        + (kg * 16 + bf4);
    const float4* vvp = (const float4*)(V   + (size_t)bh  * L_SEQ * D_HEAD)
                        + (kg * 16 + bf4);
    float4 pf_t = __ldcs(tvp);       // in flight across the softmax window
    float4 pf_v = __ldg(vvp);
    tvp += 256;
    vvp += 256;

    __syncthreads();

    // ---- Softmax over k (256 values, one per thread) ----
    const float v = esh[tid];
    float m = v;
    #pragma unroll
    for (int o = 16; o > 0; o >>= 1)
        m = fmaxf(m, __shfl_xor_sync(0xffffffffu, m, o));
    if (lane == 0) red[w] = m;
    __syncthreads();
    if (tid == 0) {
        float mm = red[0];
        #pragma unroll
        for (int i = 1; i < 8; ++i) mm = fmaxf(mm, red[i]);
        red[0] = mm;
    }
    __syncthreads();
    m = red[0];
    __syncthreads();

    const float e = __expf(v - m);
    float s = e;
    #pragma unroll
    for (int o = 16; o > 0; o >>= 1)
        s += __shfl_xor_sync(0xffffffffu, s, o);
    if (lane == 0) red[w] = s;
    __syncthreads();
    if (tid == 0) {
        float ss = red[0];
        #pragma unroll
        for (int i = 1; i < 8; ++i) ss += red[i];
        red[0] = 1.0f / ss;
    }
    __syncthreads();
    const float a = e * red[0];
    __syncthreads();
    esh[tid] = a;
    if (write_aw) AW[(size_t)bhq * L_SEQ + tid] = a;
    __syncthreads();

    // ---- Phase B: O[q,:] = sum_k a[k] * (V[k,:] + TMV[q,k,:]) ----
    float4 acc;
    {
        const float ak0 = esh[kg];               // consume prefetched iteration
        acc.x = ak0 * (pf_t.x + pf_v.x);
        acc.y = ak0 * (pf_t.y + pf_v.y);
        acc.z = ak0 * (pf_t.z + pf_v.z);
        acc.w = ak0 * (pf_t.w + pf_v.w);
    }

    #pragma unroll 3
    for (int k = kg + 16; k < L_SEQ; k += 16) {
        const float ak = esh[k];
        float4 t  = __ldcs(tvp);     // streaming
        float4 vv = __ldg(vvp);      // hot in L2
        tvp += 256;
        vvp += 256;
        acc.x += ak * (t.x + vv.x);
        acc.y += ak * (t.y + vv.y);
        acc.z += ak * (t.z + vv.z);
        acc.w += ak * (t.w + vv.w);
    }
    acc_sh[kg][bf4] = acc;
    __syncthreads();

    if (tid < 16) {
        float4 r = acc_sh[0][tid];
        #pragma unroll
        for (int g = 1; g < 16; ++g) {
            float4 p = acc_sh[g][tid];
            r.x += p.x; r.y += p.y; r.z += p.z; r.w += p.w;
        }
        ((float4*)(O + (size_t)bhq * D_HEAD))[tid] = r;
    }
}

extern "C" void kernel_launch(void* const* d_in, const int* in_sizes, int n_in,
                              void* d_out, int out_size)
{
    const float*         Q   = (const float*)d_in[0];
    const float*         Km  = (const float*)d_in[1];
    const float*         V   = (const float*)d_in[2];
    const float*         TMK = (const float*)d_in[3];
    const float*         TMV = (const float*)d_in[4];
    const float*         AM  = (const float*)d_in[5];
    const unsigned char* PM  = (const unsigned char*)d_in[6];

    const int L = 256, D = 64;
    const int b = in_sizes[6] / L;                 // padding_mask is [b, L]
    const int h = in_sizes[0] / (b * L * D);       // Q is [b, h, L, D]

    const int nO  = b * h * L * D;
    const int nAW = b * h * L * L;

    float* O  = (float*)d_out;
    float* AW = O + nO;
    const int write_aw = (out_size >= nO + nAW) ? 1 : 0;

    tasdp_kernel<<<b * h * L, 256>>>(Q, Km, V, TMK, TMV, AM, PM, O, AW, h, write_aw);
}